// round 2
// baseline (speedup 1.0000x reference)
#include <cuda_runtime.h>
#include <cstdint>

// ---------------------------------------------------------------------------
// OctonionHeadMixer: y[b,i,t,e] = sum_{j,d} x[b,j,t,d] * sign[i,j]*W[widx[i,j]][d,e]*beta[e]
// == per-b GEMM: Y[4096 x 1024] = X[4096 x 1024(j,d)] @ Wf[1024(j,d) x 1024(i,e)]
// Wf built once per launch (4MB, L2-resident), tf32-rounded with bias compensation.
// GEMM: mma.sync.m16n8k8 tf32, cp.async 3-stage pipeline.
// ---------------------------------------------------------------------------

constexpr int NS = 3;                 // pipeline stages
constexpr int AS_LD = 36;             // A smem row stride (floats): (4*row+col)%32 distinct
constexpr int BS_LD = 136;            // B smem row stride (floats): (8*k+n)%32 distinct
constexpr int A_FLOATS = 128 * AS_LD; // 4608
constexpr int B_FLOATS = 32 * BS_LD;  // 4352
constexpr int STAGE_FLOATS = A_FLOATS + B_FLOATS; // 8960
constexpr int SMEM_BYTES = NS * STAGE_FLOATS * 4; // 107520

// Fused weight: Wf[k=(j,d)][n=(i,e)], tf32-rounded, beta + sign + A-trunc compensation folded in.
__device__ float g_Wf[1024 * 1024];

__constant__ float c_sign[64] = {
 +1,-1,-1,-1,-1,-1,-1,-1,
 +1,+1,+1,-1,+1,-1,-1,+1,
 +1,-1,+1,+1,+1,+1,-1,-1,
 +1,+1,-1,+1,+1,-1,+1,-1,
 +1,-1,-1,-1,+1,+1,+1,+1,
 +1,+1,-1,+1,-1,+1,-1,+1,
 +1,+1,+1,-1,-1,+1,+1,-1,
 +1,-1,+1,+1,-1,-1,+1,+1};
__constant__ int c_widx[64] = {
 0,1,2,3,4,5,6,7,
 1,0,3,2,5,4,7,6,
 2,3,0,1,6,7,4,5,
 3,2,1,0,7,6,5,4,
 4,5,6,7,0,1,2,3,
 5,4,7,6,1,0,3,2,
 6,7,4,5,2,3,0,1,
 7,6,5,4,3,2,1,0};

// Compensation for tf32 truncation (RZ) of the A operand inside HMMA:
// mean relative loss = 2^-11 * E[1/m] (m log-uniform in [1,2)) = 3.52e-4.
#define A_TRUNC_COMP 1.000352f

__global__ void prep_wf_kernel(const float* __restrict__ W,
                               const float* __restrict__ beta) {
    int idx = blockIdx.x * blockDim.x + threadIdx.x;   // 0 .. 1M-1
    int n = idx & 1023;          // (i,e)
    int k = idx >> 10;           // (j,d)
    int i = n >> 7, e = n & 127;
    int j = k >> 7, d = k & 127;
    float v = c_sign[i * 8 + j] * W[(c_widx[i * 8 + j] << 14) + d * 128 + e]
              * beta[e] * A_TRUNC_COMP;
    uint32_t t;
    asm("cvt.rna.tf32.f32 %0, %1;" : "=r"(t) : "f"(v));
    g_Wf[(size_t)k * 1024 + n] = __uint_as_float(t);
}

__device__ __forceinline__ void cp_async16(uint32_t dst, const void* src) {
    asm volatile("cp.async.cg.shared.global [%0], [%1], 16;\n"
                 :: "r"(dst), "l"(src) : "memory");
}
__device__ __forceinline__ void cp_commit() {
    asm volatile("cp.async.commit_group;\n" ::: "memory");
}
template <int N>
__device__ __forceinline__ void cp_wait() {
    asm volatile("cp.async.wait_group %0;\n" :: "n"(N) : "memory");
}

__global__ __launch_bounds__(256, 2)
void octo_gemm_kernel(const float* __restrict__ x, float* __restrict__ y) {
    extern __shared__ float sm[];
    const int tid = threadIdx.x;
    const int lane = tid & 31;
    const int warp = tid >> 5;
    const int warp_m = warp & 1;   // 2 warps over M (64 each)
    const int warp_n = warp >> 1;  // 4 warps over N (32 each)

    const int nt_blk = blockIdx.x;     // 0..7  -> head i, n0 = i*128
    const int mt_blk = blockIdx.y;     // 0..31 -> t tile
    const int b      = blockIdx.z;     // 0..7
    const int t0 = mt_blk * 128;
    const int n0 = nt_blk * 128;

    // cp.async thread mapping
    const int ar = tid >> 3;            // A: 32 rows per pass, 8 x 16B per 128B row
    const int ac = (tid & 7) * 4;
    const int br = tid >> 5;            // B: 8 rows per pass, 32 x 16B per 512B row
    const int bc = (tid & 31) * 4;

    const float* xb = x + (size_t)b * (8u * 4096u * 128u);

    auto issue_stage = [&](int kc) {
        const int s = kc % NS;
        float* As = sm + s * STAGE_FLOATS;
        float* Bs = As + A_FLOATS;
        const int j = kc >> 2;
        const int d0 = (kc & 3) * 32;
        const float* srcA = xb + ((size_t)j * 4096 + t0) * 128 + d0;
        const float* srcB = g_Wf + (size_t)(kc * 32) * 1024 + n0;
        #pragma unroll
        for (int it = 0; it < 4; it++) {
            uint32_t da = (uint32_t)__cvta_generic_to_shared(
                As + (ar + 32 * it) * AS_LD + ac);
            cp_async16(da, srcA + (size_t)(ar + 32 * it) * 128 + ac);
            uint32_t db = (uint32_t)__cvta_generic_to_shared(
                Bs + (br + 8 * it) * BS_LD + bc);
            cp_async16(db, srcB + (size_t)(br + 8 * it) * 1024 + bc);
        }
    };

    // prologue: NS-1 = 2 stages in flight
    issue_stage(0); cp_commit();
    issue_stage(1); cp_commit();

    float acc[4][4][4];
    #pragma unroll
    for (int mt = 0; mt < 4; mt++)
        #pragma unroll
        for (int nt = 0; nt < 4; nt++)
            #pragma unroll
            for (int c = 0; c < 4; c++) acc[mt][nt][c] = 0.0f;

    for (int kc = 0; kc < 32; kc++) {
        cp_wait<NS - 2>();     // stage kc ready (<=1 group pending)
        __syncthreads();

        if (kc + 2 < 32) issue_stage(kc + 2);
        cp_commit();           // always commit (empty groups at the tail keep counts uniform)

        const float* As = sm + (kc % NS) * STAGE_FLOATS;
        const float* Bs = As + A_FLOATS;

        #pragma unroll
        for (int ks = 0; ks < 4; ks++) {
            uint32_t a[4][4], bb[4][2];
            const int arow = warp_m * 64 + (lane >> 2);
            const int acol = ks * 8 + (lane & 3);
            #pragma unroll
            for (int mt = 0; mt < 4; mt++) {
                const float* ap = As + (arow + mt * 16) * AS_LD + acol;
                a[mt][0] = __float_as_uint(ap[0]);
                a[mt][1] = __float_as_uint(ap[8 * AS_LD]);
                a[mt][2] = __float_as_uint(ap[4]);
                a[mt][3] = __float_as_uint(ap[8 * AS_LD + 4]);
            }
            const int brow = ks * 8 + (lane & 3);
            const int bcol = warp_n * 32 + (lane >> 2);
            #pragma unroll
            for (int nt = 0; nt < 4; nt++) {
                const float* bp = Bs + brow * BS_LD + bcol + nt * 8;
                bb[nt][0] = __float_as_uint(bp[0]);
                bb[nt][1] = __float_as_uint(bp[4 * BS_LD]);
            }
            #pragma unroll
            for (int mt = 0; mt < 4; mt++)
                #pragma unroll
                for (int nt = 0; nt < 4; nt++)
                    asm volatile(
                        "mma.sync.aligned.m16n8k8.row.col.f32.tf32.tf32.f32 "
                        "{%0,%1,%2,%3}, {%4,%5,%6,%7}, {%8,%9}, {%0,%1,%2,%3};\n"
                        : "+f"(acc[mt][nt][0]), "+f"(acc[mt][nt][1]),
                          "+f"(acc[mt][nt][2]), "+f"(acc[mt][nt][3])
                        : "r"(a[mt][0]), "r"(a[mt][1]), "r"(a[mt][2]), "r"(a[mt][3]),
                          "r"(bb[nt][0]), "r"(bb[nt][1]));
        }
    }

    // epilogue: y[b][i=nt_blk][t][e]
    float* yb = y + ((size_t)b * 8 + nt_blk) * 4096u * 128u;
    #pragma unroll
    for (int mt = 0; mt < 4; mt++) {
        const int row = t0 + warp_m * 64 + mt * 16 + (lane >> 2);
        #pragma unroll
        for (int nt = 0; nt < 4; nt++) {
            const int e = warp_n * 32 + nt * 8 + (lane & 3) * 2;
            float2 v0 = make_float2(acc[mt][nt][0], acc[mt][nt][1]);
            float2 v1 = make_float2(acc[mt][nt][2], acc[mt][nt][3]);
            *reinterpret_cast<float2*>(yb + (size_t)row * 128 + e) = v0;
            *reinterpret_cast<float2*>(yb + (size_t)(row + 8) * 128 + e) = v1;
        }
    }
}

extern "C" void kernel_launch(void* const* d_in, const int* in_sizes, int n_in,
                              void* d_out, int out_size) {
    const float* x    = (const float*)d_in[0];   // [8,8,4096,128] fp32
    const float* W    = (const float*)d_in[1];   // [8,128,128] fp32
    const float* beta = (const float*)d_in[2];   // [128] fp32
    float* y = (float*)d_out;                    // [8,8,4096,128] fp32

    (void)in_sizes; (void)n_in; (void)out_size;

    cudaFuncSetAttribute(octo_gemm_kernel,
                         cudaFuncAttributeMaxDynamicSharedMemorySize, SMEM_BYTES);

    prep_wf_kernel<<<4096, 256>>>(W, beta);

    dim3 grid(8, 32, 8);   // (ntile fastest -> 8 CTAs share each A tile in L2, mtile, b)
    octo_gemm_kernel<<<grid, 256, SMEM_BYTES>>>(x, y);
}

// round 4
// speedup vs baseline: 1.0440x; 1.0440x over previous
#include <cuda_runtime.h>
#include <cstdint>

// ---------------------------------------------------------------------------
// y[b,i,t,e] = sum_{j,d} x[b,j,t,d] * sign[i,j]*W[widx[i,j]][d,e]*beta[e]
// == per-b GEMM: Y[4096 x 1024] = X[4096 x 1024(k=j,d)] @ Wf[k][n=(i,e)]
//
// sm_100 (non-'a' target): tcgen05 unavailable -> legacy mma.sync tf32 path.
// B operand is pre-permuted in global memory into per-thread fragment order so
// the GEMM kernel stages it with linear cp.async and loads frags with LDS.64.
// A+B fragments are register double-buffered across k-steps to hide LDS latency.
// ---------------------------------------------------------------------------

constexpr int NS = 3;                 // pipeline stages
constexpr int AS_LD = 36;             // A smem row stride (floats), conflict-free
constexpr int A_FLOATS = 128 * AS_LD; // 4608
constexpr int B_FLOATS = 4096;        // 32k x 128n in fragment order (16KB)
constexpr int STAGE_FLOATS = A_FLOATS + B_FLOATS;   // 8704
constexpr int SMEM_BYTES = NS * STAGE_FLOATS * 4;   // 104448 -> 2 CTAs/SM

// B operand, fragment-order layout:
// gB[n_blk(8)][kc(32)][ks(4)][warp_n(4)][nt(4)][lane(32)][pair(2)]
//   value(pair p) = Wf[k = kc*32+ks*8+(lane&3)+4p][n = n_blk*128+warp_n*32+nt*8+(lane>>2)]
__device__ float g_WfB[1024 * 1024];

__constant__ float c_sign[64] = {
 +1,-1,-1,-1,-1,-1,-1,-1,
 +1,+1,+1,-1,+1,-1,-1,+1,
 +1,-1,+1,+1,+1,+1,-1,-1,
 +1,+1,-1,+1,+1,-1,+1,-1,
 +1,-1,-1,-1,+1,+1,+1,+1,
 +1,+1,-1,+1,-1,+1,-1,+1,
 +1,+1,+1,-1,-1,+1,+1,-1,
 +1,-1,+1,+1,-1,-1,+1,+1};
__constant__ int c_widx[64] = {
 0,1,2,3,4,5,6,7,
 1,0,3,2,5,4,7,6,
 2,3,0,1,6,7,4,5,
 3,2,1,0,7,6,5,4,
 4,5,6,7,0,1,2,3,
 5,4,7,6,1,0,3,2,
 6,7,4,5,2,3,0,1,
 7,6,5,4,3,2,1,0};

// Compensation for tf32 RZ-truncation of the A operand inside the tensor core:
// mean relative loss = 2^-11 * E[1/m], m log-uniform in [1,2) -> 3.52e-4.
#define A_TRUNC_COMP 1.000352f

// ---------------- PTX helpers ----------------
__device__ __forceinline__ void cp_async16(uint32_t dst, const void* src) {
    asm volatile("cp.async.cg.shared.global [%0], [%1], 16;\n"
                 :: "r"(dst), "l"(src) : "memory");
}
__device__ __forceinline__ void cp_commit() {
    asm volatile("cp.async.commit_group;\n" ::: "memory");
}
template <int N>
__device__ __forceinline__ void cp_wait() {
    asm volatile("cp.async.wait_group %0;\n" :: "n"(N) : "memory");
}
__device__ __forceinline__ uint32_t smem_u32(const void* p) {
    uint32_t a;
    asm("{ .reg .u64 t; cvta.to.shared.u64 t, %1; cvt.u32.u64 %0, t; }"
        : "=r"(a) : "l"(p));
    return a;
}

// ---------------- Wf prep: fragment-order B ----------------
__global__ void prep_wf_kernel(const float* __restrict__ W,
                               const float* __restrict__ beta) {
    const int idx = blockIdx.x * 256 + threadIdx.x;   // 0 .. 512K-1 (pairs)
    const int lane = idx & 31;
    const int nt   = (idx >> 5) & 3;
    const int wn   = (idx >> 7) & 3;
    const int ks   = (idx >> 9) & 3;
    const int kc   = (idx >> 11) & 31;
    const int nb   = idx >> 16;

    const int n  = nb * 128 + wn * 32 + nt * 8 + (lane >> 2);
    const int k0 = kc * 32 + ks * 8 + (lane & 3);
    const int i = n >> 7, e = n & 127;

    float2 out;
    #pragma unroll
    for (int p = 0; p < 2; p++) {
        const int k = k0 + 4 * p;
        const int j = k >> 7, d = k & 127;
        const float v = c_sign[i * 8 + j] * W[(c_widx[i * 8 + j] << 14) + d * 128 + e]
                        * beta[e] * A_TRUNC_COMP;
        uint32_t t;
        asm("cvt.rna.tf32.f32 %0, %1;" : "=r"(t) : "f"(v));
        (p ? out.y : out.x) = __uint_as_float(t);
    }
    reinterpret_cast<float2*>(g_WfB)[idx] = out;
}

// ---------------- main GEMM ----------------
__global__ __launch_bounds__(256, 2)
void octo_gemm_kernel(const float* __restrict__ x, float* __restrict__ y) {
    extern __shared__ float sm[];
    const uint32_t sbase = smem_u32(sm);
    const int tid = threadIdx.x;
    const int lane = tid & 31;
    const int warp = tid >> 5;
    const int warp_m = warp & 1;   // 2 warps over M (64 rows each)
    const int warp_n = warp >> 1;  // 4 warps over N (32 cols each)

    const int nb = blockIdx.x;         // 0..7  -> head i, n0 = nb*128
    const int t0 = blockIdx.y * 128;   // t tile
    const int b  = blockIdx.z;

    // cp.async thread mapping (A): 1024 16B-chunks, 4 per thread
    const int ar = tid >> 3;           // row 0..31 per pass
    const int ac = tid & 7;            // 16B chunk in row

    const float* xb = x + (size_t)b * (8u * 4096u * 128u);
    const float* gBblk = g_WfB + (size_t)nb * (32u * 4096u);

    auto issue_stage = [&](int kc) {
        const int s = kc % NS;
        const uint32_t a_base = sbase + (uint32_t)(s * STAGE_FLOATS) * 4u;
        const uint32_t b_base = a_base + A_FLOATS * 4u;
        const int j = kc >> 2;
        const int d0 = (kc & 3) * 32;
        const float* srcA = xb + ((size_t)j * 4096 + t0) * 128 + d0;
        const float* srcB = gBblk + (size_t)kc * 4096;
        #pragma unroll
        for (int it = 0; it < 4; it++) {          // A: 128 rows x 8 chunks
            const int r = ar + 32 * it;
            cp_async16(a_base + (uint32_t)(r * AS_LD + ac * 4) * 4u,
                       srcA + (size_t)r * 128 + ac * 4);
        }
        #pragma unroll
        for (int it = 0; it < 4; it++) {          // B: 16KB linear
            const int id = tid + 256 * it;
            cp_async16(b_base + (uint32_t)id * 16u, srcB + id * 4);
        }
    };

    issue_stage(0); cp_commit();
    issue_stage(1); cp_commit();

    float acc[4][4][4];
    #pragma unroll
    for (int mt = 0; mt < 4; mt++)
        #pragma unroll
        for (int nt = 0; nt < 4; nt++)
            #pragma unroll
            for (int c = 0; c < 4; c++) acc[mt][nt][c] = 0.0f;

    // per-thread fragment addresses (within a stage, byte offsets from stage A base)
    const uint32_t a_off0 = (uint32_t)((warp_m * 64 + (lane >> 2)) * AS_LD + (lane & 3)) * 4u;
    const uint32_t b_off0 = (uint32_t)(A_FLOATS + warp_n * 256 + lane * 2) * 4u;

    uint32_t aF[2][4][4];   // [buf][mt][reg]
    uint32_t bF[2][4][2];   // [buf][nt][reg]

    for (int kc = 0; kc < 32; kc++) {
        cp_wait<NS - 2>();
        __syncthreads();
        if (kc + 2 < 32) issue_stage(kc + 2);
        cp_commit();                      // empty tail groups keep counts uniform

        const uint32_t stg = sbase + (uint32_t)((kc % NS) * STAGE_FLOATS) * 4u;
        const uint32_t aS = stg + a_off0;
        const uint32_t bS = stg + b_off0;

        // prefetch ks=0 fragments
        #pragma unroll
        for (int mt = 0; mt < 4; mt++) {
            const uint32_t ad = aS + (uint32_t)(mt * 16 * AS_LD) * 4u;
            asm volatile("ld.shared.b32 %0, [%1];"      : "=r"(aF[0][mt][0]) : "r"(ad));
            asm volatile("ld.shared.b32 %0, [%1+1152];" : "=r"(aF[0][mt][1]) : "r"(ad)); // +8*36*4
            asm volatile("ld.shared.b32 %0, [%1+16];"   : "=r"(aF[0][mt][2]) : "r"(ad));
            asm volatile("ld.shared.b32 %0, [%1+1168];" : "=r"(aF[0][mt][3]) : "r"(ad));
        }
        #pragma unroll
        for (int nt = 0; nt < 4; nt++)
            asm volatile("ld.shared.v2.b32 {%0,%1}, [%2];"
                         : "=r"(bF[0][nt][0]), "=r"(bF[0][nt][1])
                         : "r"(bS + (uint32_t)(nt * 64) * 4u));

        #pragma unroll
        for (int ks = 0; ks < 4; ks++) {
            const int cur = ks & 1, nxt = cur ^ 1;
            if (ks < 3) {   // prefetch ks+1 fragments before the MMAs of ks
                const uint32_t ad1 = aS + (uint32_t)((ks + 1) * 8) * 4u;
                #pragma unroll
                for (int mt = 0; mt < 4; mt++) {
                    const uint32_t ad = ad1 + (uint32_t)(mt * 16 * AS_LD) * 4u;
                    asm volatile("ld.shared.b32 %0, [%1];"      : "=r"(aF[nxt][mt][0]) : "r"(ad));
                    asm volatile("ld.shared.b32 %0, [%1+1152];" : "=r"(aF[nxt][mt][1]) : "r"(ad));
                    asm volatile("ld.shared.b32 %0, [%1+16];"   : "=r"(aF[nxt][mt][2]) : "r"(ad));
                    asm volatile("ld.shared.b32 %0, [%1+1168];" : "=r"(aF[nxt][mt][3]) : "r"(ad));
                }
                const uint32_t bd1 = bS + (uint32_t)((ks + 1) * 1024) * 4u;
                #pragma unroll
                for (int nt = 0; nt < 4; nt++)
                    asm volatile("ld.shared.v2.b32 {%0,%1}, [%2];"
                                 : "=r"(bF[nxt][nt][0]), "=r"(bF[nxt][nt][1])
                                 : "r"(bd1 + (uint32_t)(nt * 64) * 4u));
            }
            #pragma unroll
            for (int mt = 0; mt < 4; mt++)
                #pragma unroll
                for (int nt = 0; nt < 4; nt++)
                    asm volatile(
                        "mma.sync.aligned.m16n8k8.row.col.f32.tf32.tf32.f32 "
                        "{%0,%1,%2,%3}, {%4,%5,%6,%7}, {%8,%9}, {%0,%1,%2,%3};\n"
                        : "+f"(acc[mt][nt][0]), "+f"(acc[mt][nt][1]),
                          "+f"(acc[mt][nt][2]), "+f"(acc[mt][nt][3])
                        : "r"(aF[cur][mt][0]), "r"(aF[cur][mt][1]),
                          "r"(aF[cur][mt][2]), "r"(aF[cur][mt][3]),
                          "r"(bF[cur][nt][0]), "r"(bF[cur][nt][1]));
        }
    }

    // epilogue: y[b][i=nb][t][e]
    float* yb = y + ((size_t)b * 8 + nb) * 4096u * 128u;
    #pragma unroll
    for (int mt = 0; mt < 4; mt++) {
        const int row = t0 + warp_m * 64 + mt * 16 + (lane >> 2);
        #pragma unroll
        for (int nt = 0; nt < 4; nt++) {
            const int e = warp_n * 32 + nt * 8 + (lane & 3) * 2;
            *reinterpret_cast<float2*>(yb + (size_t)row * 128 + e) =
                make_float2(acc[mt][nt][0], acc[mt][nt][1]);
            *reinterpret_cast<float2*>(yb + (size_t)(row + 8) * 128 + e) =
                make_float2(acc[mt][nt][2], acc[mt][nt][3]);
        }
    }
}

extern "C" void kernel_launch(void* const* d_in, const int* in_sizes, int n_in,
                              void* d_out, int out_size) {
    const float* x    = (const float*)d_in[0];   // [8,8,4096,128] fp32
    const float* W    = (const float*)d_in[1];   // [8,128,128] fp32
    const float* beta = (const float*)d_in[2];   // [128] fp32
    float* y = (float*)d_out;                    // [8,8,4096,128] fp32
    (void)in_sizes; (void)n_in; (void)out_size;

    cudaFuncSetAttribute(octo_gemm_kernel,
                         cudaFuncAttributeMaxDynamicSharedMemorySize, SMEM_BYTES);

    prep_wf_kernel<<<2048, 256>>>(W, beta);

    dim3 grid(8, 32, 8);   // n-tiles fastest: 8 CTAs share each x tile in L2
    octo_gemm_kernel<<<grid, 256, SMEM_BYTES>>>(x, y);
}